// round 8
// baseline (speedup 1.0000x reference)
#include <cuda_runtime.h>
#include <cstdint>

#define DDIM 512
#define KDIM 512
#define BM   64
#define NTH  512
#define NCH  16      // K chunks of 32 fp8

// static scratch (no allocations allowed)
__device__ uint8_t g_cb8[KDIM * DDIM];   // clusters e4m3, scaled x64, row-major [K][D]
__device__ float g_c2[KDIM];             // unscaled ||c||^2

// ---- smem layout (bytes, dynamic) ----
#define BSTAGEB 16384u                // 512 rows * 32B (k32 fp8), XOR swizzle, no pad
#define OFF_A   0u                    // 64 rows * 512B = 32768, resident (e4m3 x)
#define OFF_B   32768u                // 2 * 16384 -> 65536
#define OFF_C2  65536u                // 512*4 -> 67584
#define OFF_X2  67584u                // 64*4  -> 67840
#define OFF_RS  67840u                // 8*64*4 -> 69888
#define SMEM_TOTAL 69888u

// ---------------- helpers ----------------
__device__ __forceinline__ float frcp(float a) {
    float r; asm("rcp.approx.ftz.f32 %0, %1;" : "=f"(r) : "f"(a)); return r;
}
// pack 4 floats -> 4 e4m3 bytes (f0 = lowest byte)
__device__ __forceinline__ uint32_t pk8(float4 u) {
    unsigned short lo, hi;
    asm("cvt.rn.satfinite.e4m3x2.f32 %0, %1, %2;" : "=h"(lo) : "f"(u.y), "f"(u.x));
    asm("cvt.rn.satfinite.e4m3x2.f32 %0, %1, %2;" : "=h"(hi) : "f"(u.w), "f"(u.z));
    return (uint32_t)lo | ((uint32_t)hi << 16);
}
__device__ __forceinline__ void cp16(uint32_t dst, const void* src) {
    asm volatile("cp.async.cg.shared.global [%0], [%1], 16;"
                 :: "r"(dst), "l"(__cvta_generic_to_global(src)) : "memory");
}
#define CP_COMMIT() asm volatile("cp.async.commit_group;" ::: "memory")
template <int N>
__device__ __forceinline__ void cp_wait() {
    asm volatile("cp.async.wait_group %0;" :: "n"(N) : "memory");
}
__device__ __forceinline__ void ldsm4(uint32_t* r, uint32_t a) {
    asm volatile("ldmatrix.sync.aligned.m8n8.x4.shared.b16 {%0,%1,%2,%3}, [%4];"
                 : "=r"(r[0]), "=r"(r[1]), "=r"(r[2]), "=r"(r[3]) : "r"(a));
}
// fp8 e4m3 MMA, f32 accumulators
__device__ __forceinline__ void mma_fp8(float* c, const uint32_t* a, uint32_t b0, uint32_t b1) {
    asm volatile("mma.sync.aligned.m16n8k32.row.col.f32.e4m3.e4m3.f32 "
                 "{%0,%1,%2,%3}, {%4,%5,%6,%7}, {%8,%9}, {%0,%1,%2,%3};"
                 : "+f"(c[0]), "+f"(c[1]), "+f"(c[2]), "+f"(c[3])
                 : "r"(a[0]), "r"(a[1]), "r"(a[2]), "r"(a[3]), "r"(b0), "r"(b1));
}

// ---------------- prep: clusters -> e4m3 (x64), c2 fp32 ----------------
__global__ void prep_kernel(const float* __restrict__ clusters) {
    int k = blockIdx.x, tid = threadIdx.x;
    const float* row = clusters + (size_t)k * DDIM;
    float s = 0.f;
    for (int d = tid; d < DDIM; d += 128) {
        float v = row[d];
        s += v * v;
        unsigned short t;
        asm("cvt.rn.satfinite.e4m3x2.f32 %0, %1, %2;" : "=h"(t) : "f"(0.f), "f"(v * 64.f));
        g_cb8[(size_t)k * DDIM + d] = (uint8_t)t;
    }
    #pragma unroll
    for (int o = 16; o > 0; o >>= 1) s += __shfl_xor_sync(0xffffffffu, s, o);
    __shared__ float red[4];
    if ((tid & 31) == 0) red[tid >> 5] = s;
    __syncthreads();
    if (tid == 0) g_c2[k] = red[0] + red[1] + red[2] + red[3];
}

// ---------------- main fused kernel ----------------
// CTA: 64 rows x all 512 cols. 512 threads, warp grid 2(M) x 8(N), warp tile 32x64.
// e4m3 operands (c scaled x64), f32 accumulators. A resident; B streamed k32 2-stage.
__global__ void __launch_bounds__(NTH, 1)
cluster_kernel(const float* __restrict__ x, float* __restrict__ out) {
    extern __shared__ char smem[];
    char*  smA = smem + OFF_A;
    float* c2s = (float*)(smem + OFF_C2);
    float* x2s = (float*)(smem + OFF_X2);
    float* rss = (float*)(smem + OFF_RS);

    const int tid = threadIdx.x, lane = tid & 31, wid = tid >> 5;
    const int wm = wid & 1, wn = wid >> 1;          // 2 x 8 warp grid
    const long row0 = (long)blockIdx.x * BM;
    const float* xblk = x + row0 * DDIM;

    const uint32_t sA = (uint32_t)__cvta_generic_to_shared(smA);
    const uint32_t sB = (uint32_t)__cvta_generic_to_shared(smem + OFF_B);

    // B loader: chunk c = k-bytes [c*32, c*32+32) of all 512 cluster rows (16 KB)
    // smem: row*32 + (seg16 ^ ((row&4)<<2))  -- conflict-free XOR swizzle
    auto loadB = [&](int c, int s) {
        #pragma unroll
        for (int i = 0; i < 2; i++) {
            int idx = tid + i * NTH;                // 0..1023
            int brow = idx >> 1, seg = (idx & 1) << 4;
            uint32_t dst = sB + s * BSTAGEB + brow * 32 + (seg ^ ((brow & 4) << 2));
            const char* src = (const char*)g_cb8 + (size_t)brow * DDIM + c * 32 + seg;
            cp16(dst, src);
        }
        CP_COMMIT();
    };

    loadB(0, 0);   // prefetch chunk 0 while converting A

    for (int i = tid; i < KDIM; i += NTH) c2s[i] = g_c2[i];

    // ---- A: x fp32 -> e4m3 into swizzled resident smem (512B rows), + ||x||^2 ----
    // Swizzle: byte-col cb: cb ^ ((row&7)<<4)  (toggles the 16B-slot within 128B)
    {
        const int arow = tid >> 3, a8 = tid & 7;    // 8 threads/row, 64 floats each
        const float* src = xblk + (size_t)arow * DDIM + a8 * 64;
        float x2a = 0.f;
        #pragma unroll
        for (int j = 0; j < 4; j++) {
            float4 f0 = *(const float4*)(src + j * 16);
            float4 f1 = *(const float4*)(src + j * 16 + 4);
            float4 f2 = *(const float4*)(src + j * 16 + 8);
            float4 f3 = *(const float4*)(src + j * 16 + 12);
            x2a += f0.x*f0.x + f0.y*f0.y + f0.z*f0.z + f0.w*f0.w;
            x2a += f1.x*f1.x + f1.y*f1.y + f1.z*f1.z + f1.w*f1.w;
            x2a += f2.x*f2.x + f2.y*f2.y + f2.z*f2.z + f2.w*f2.w;
            x2a += f3.x*f3.x + f3.y*f3.y + f3.z*f3.z + f3.w*f3.w;
            uint4 w = make_uint4(pk8(f0), pk8(f1), pk8(f2), pk8(f3));
            uint32_t cb = (uint32_t)(a8 * 64 + j * 16);
            *(uint4*)(smA + arow * 512 + (cb ^ ((arow & 7u) << 4))) = w;
        }
        x2a += __shfl_xor_sync(0xffffffffu, x2a, 1);
        x2a += __shfl_xor_sync(0xffffffffu, x2a, 2);
        x2a += __shfl_xor_sync(0xffffffffu, x2a, 4);
        if ((tid & 7) == 0) x2s[arow] = x2a;
    }

    float acc[2][8][4];
    #pragma unroll
    for (int mt = 0; mt < 2; mt++)
        #pragma unroll
        for (int nt = 0; nt < 8; nt++)
            #pragma unroll
            for (int j = 0; j < 4; j++) acc[mt][nt][j] = 0.f;

    const uint32_t lmr = lane & 15, lmc = (lane >> 4) * 16;
    const uint32_t xr  = (lmr & 7u) << 4;                         // A swizzle term
    const uint32_t aro0 = sA + (uint32_t)(wm * 32 + lmr) * 512u;
    const uint32_t aro1 = sA + (uint32_t)(wm * 32 + 16 + lmr) * 512u;
    // B base: row = wn*64 + lmr (bt*16 rows -> +bt*512 bytes, swizzle term lane-const)
    const uint32_t bro = (uint32_t)(wn * 64 + lmr) * 32u + (lmc ^ ((lmr & 4u) << 2));

    // ---- mainloop: 16 K-chunks (k32 fp8), A resident, B double-buffered ----
    #pragma unroll 1
    for (int c = 0; c < NCH; c++) {
        cp_wait<0>();
        __syncthreads();                       // chunk c visible; other stage free
        if (c + 1 < NCH) loadB(c + 1, (c + 1) & 1);

        const uint32_t acb = ((uint32_t)(c * 32) + lmc) ^ xr;
        uint32_t a0[4], a1[4];
        ldsm4(a0, aro0 + acb);
        ldsm4(a1, aro1 + acb);
        const uint32_t bbase = sB + (c & 1) * BSTAGEB + bro;
        #pragma unroll
        for (int bt = 0; bt < 4; bt++) {
            uint32_t b[4];
            ldsm4(b, bbase + bt * 512);
            mma_fp8(acc[0][2 * bt + 0], a0, b[0], b[2]);
            mma_fp8(acc[0][2 * bt + 1], a0, b[1], b[3]);
            mma_fp8(acc[1][2 * bt + 0], a1, b[0], b[2]);
            mma_fp8(acc[1][2 * bt + 1], a1, b[1], b[3]);
        }
    }

    // ---- epilogue pass 1: d2 -> q (overwrite acc), row sums ----
    // dot = acc/64  ->  d2 = x2 + c2 - acc/32
    #pragma unroll
    for (int mt = 0; mt < 2; mt++) {
        #pragma unroll
        for (int rr = 0; rr < 2; rr++) {
            const int row = wm * 32 + mt * 16 + (lane >> 2) + rr * 8;
            const float x2v = x2s[row];
            float rsum = 0.f;
            #pragma unroll
            for (int nt = 0; nt < 8; nt++) {
                const int col = wn * 64 + nt * 8 + (lane & 3) * 2;
                float d0 = fmaxf(fmaf(-0.03125f, acc[mt][nt][rr * 2 + 0], x2v + c2s[col]), 0.f);
                float d1 = fmaxf(fmaf(-0.03125f, acc[mt][nt][rr * 2 + 1], x2v + c2s[col + 1]), 0.f);
                float q0 = frcp(1.f + d0), q1 = frcp(1.f + d1);
                acc[mt][nt][rr * 2 + 0] = q0;
                acc[mt][nt][rr * 2 + 1] = q1;
                rsum += q0 + q1;
            }
            rsum += __shfl_xor_sync(0xffffffffu, rsum, 1);
            rsum += __shfl_xor_sync(0xffffffffu, rsum, 2);
            if ((lane & 3) == 0) rss[wn * 64 + row] = rsum;
        }
    }
    __syncthreads();

    // ---- epilogue pass 2: normalize and store ----
    #pragma unroll
    for (int mt = 0; mt < 2; mt++) {
        #pragma unroll
        for (int rr = 0; rr < 2; rr++) {
            const int row = wm * 32 + mt * 16 + (lane >> 2) + rr * 8;
            float s = 0.f;
            #pragma unroll
            for (int g = 0; g < 8; g++) s += rss[g * 64 + row];
            const float inv = frcp(s);
            float* orow = out + (row0 + row) * KDIM;
            #pragma unroll
            for (int nt = 0; nt < 8; nt++) {
                const int col = wn * 64 + nt * 8 + (lane & 3) * 2;
                *(float2*)&orow[col] = make_float2(acc[mt][nt][rr * 2 + 0] * inv,
                                                   acc[mt][nt][rr * 2 + 1] * inv);
            }
        }
    }
}

extern "C" void kernel_launch(void* const* d_in, const int* in_sizes, int n_in,
                              void* d_out, int out_size) {
    const float* x        = (const float*)d_in[0];
    const float* clusters = (const float*)d_in[1];
    float* out = (float*)d_out;
    int n = in_sizes[0] / DDIM;   // 131072

    cudaFuncSetAttribute(cluster_kernel, cudaFuncAttributeMaxDynamicSharedMemorySize, SMEM_TOTAL);
    prep_kernel<<<KDIM, 128>>>(clusters);
    cluster_kernel<<<n / BM, NTH, SMEM_TOTAL>>>(x, out);
}